// round 1
// baseline (speedup 1.0000x reference)
#include <cuda_runtime.h>
#include <cstdint>

// ---------------------------------------------------------------------------
// POS predictor: emb lookup -> gi GEMM -> 512-step GRU recurrence -> classifier
// B=64, T=512, E=H=1024, 3H=3072, NCLS=20
// ---------------------------------------------------------------------------

#define B_   64
#define T_   512
#define H_   1024
#define G3   3072
#define NC   20
#define NCTA2 128   // CTAs in persistent recurrence kernel (<= 148 SMs, 1 wave)
#define SLICE 8     // h-columns per recurrence CTA  (NCTA2 * SLICE = H_)

typedef unsigned long long u64;

// ------------------------- device scratch (no allocs) ----------------------
__device__ float    g_gi[(long long)T_ * B_ * G3]; // [t*64+b][3H]   (402 MB)
__device__ float    g_hT[2][H_ * B_];              // transposed h, double buf
__device__ float    g_hs[(long long)T_ * B_ * H_]; // gru_out [t*64+b][H] (128MB)
__device__ unsigned g_bar_cnt;
__device__ unsigned g_bar_flag;

// ------------------------- f32x2 helpers (Blackwell packed fp32) -----------
__device__ __forceinline__ void fma2(u64 &d, u64 a, u64 b) {
    asm("fma.rn.f32x2 %0, %1, %2, %0;" : "+l"(d) : "l"(a), "l"(b));
}
__device__ __forceinline__ u64 add2(u64 a, u64 b) {
    u64 r; asm("add.rn.f32x2 %0, %1, %2;" : "=l"(r) : "l"(a), "l"(b)); return r;
}
__device__ __forceinline__ u64 pack2(float x, float y) {
    u64 r; asm("mov.b64 %0, {%1, %2};" : "=l"(r) : "f"(x), "f"(y)); return r;
}
__device__ __forceinline__ float2 unpack2(u64 v) {
    float2 f; asm("mov.b64 {%0, %1}, %2;" : "=f"(f.x), "=f"(f.y) : "l"(v)); return f;
}

// ------------------------- grid-wide barrier (replay-safe) -----------------
__device__ __forceinline__ void grid_sync() {
    __threadfence();            // release all this thread's global writes
    __syncthreads();
    if (threadIdx.x == 0) {
        unsigned my  = *(volatile unsigned *)&g_bar_flag;
        unsigned arr = atomicAdd(&g_bar_cnt, 1u);
        if (arr == gridDim.x - 1) {
            g_bar_cnt = 0u;
            __threadfence();
            atomicAdd(&g_bar_flag, 1u);   // monotonically increasing: replay-safe
        } else {
            while (*(volatile unsigned *)&g_bar_flag == my) { __nanosleep(64); }
        }
    }
    __syncthreads();
}

// ===========================================================================
// Kernel 1: gi[t*64+b][g] = sum_k emb[x[b][t]][k] * w_ih[g][k] + b_ih[g]
// Tiled fp32 GEMM w/ fused embedding gather. BM=128, BN=64, BK=16, 256 thr,
// thread tile 8m x 4n using f32x2 along n.
// ===========================================================================
__global__ __launch_bounds__(256) void gi_gemm(const int   *__restrict__ x,
                                               const float *__restrict__ emb,
                                               const float *__restrict__ w_ih,
                                               const float *__restrict__ b_ih) {
    __shared__ __align__(16) float sA[16][128];
    __shared__ __align__(16) float sB[16][64];
    __shared__ int sTok[128];

    const int tid = threadIdx.x;
    const int g0  = blockIdx.x * 64;
    const int m0  = blockIdx.y * 128;

    if (tid < 128) {
        int m = m0 + tid;              // m = t*64 + b
        sTok[tid] = x[(m & 63) * T_ + (m >> 6)];
    }
    __syncthreads();

    const int tm = tid & 15;           // 16 groups of 8 rows
    const int tn = tid >> 4;           // 16 groups of 4 cols

    u64 acc[8][2];
#pragma unroll
    for (int i = 0; i < 8; ++i) { acc[i][0] = 0ull; acc[i][1] = 0ull; }

    for (int ko = 0; ko < H_; ko += 16) {
        // load A tile (embedding gather): 128 rows x 16 k
#pragma unroll
        for (int j = 0; j < 2; ++j) {
            int idx = tid + j * 256;
            int row = idx >> 2, q = (idx & 3) * 4;
            float4 v = *(const float4 *)(emb + (long long)sTok[row] * H_ + ko + q);
            sA[q + 0][row] = v.x; sA[q + 1][row] = v.y;
            sA[q + 2][row] = v.z; sA[q + 3][row] = v.w;
        }
        // load B tile: 64 rows (g) x 16 k
        {
            int row = tid >> 2, q = (tid & 3) * 4;
            float4 v = *(const float4 *)(w_ih + (long long)(g0 + row) * H_ + ko + q);
            sB[q + 0][row] = v.x; sB[q + 1][row] = v.y;
            sB[q + 2][row] = v.z; sB[q + 3][row] = v.w;
        }
        __syncthreads();
#pragma unroll
        for (int k = 0; k < 16; ++k) {
            float a[8];
            *(float4 *)&a[0] = *(const float4 *)&sA[k][tm * 8];
            *(float4 *)&a[4] = *(const float4 *)&sA[k][tm * 8 + 4];
            ulonglong2 bv = *(const ulonglong2 *)&sB[k][tn * 4];
#pragma unroll
            for (int i = 0; i < 8; ++i) {
                u64 aa = pack2(a[i], a[i]);
                fma2(acc[i][0], aa, bv.x);
                fma2(acc[i][1], aa, bv.y);
            }
        }
        __syncthreads();
    }

    float4 bias = *(const float4 *)(b_ih + g0 + tn * 4);
#pragma unroll
    for (int i = 0; i < 8; ++i) {
        float2 p0 = unpack2(acc[i][0]);
        float2 p1 = unpack2(acc[i][1]);
        float4 o;
        o.x = p0.x + bias.x; o.y = p0.y + bias.y;
        o.z = p1.x + bias.z; o.w = p1.y + bias.w;
        int m = m0 + tm * 8 + i;
        *(float4 *)(g_gi + (long long)m * G3 + g0 + tn * 4) = o;
    }
}

// ===========================================================================
// Kernel 2: persistent GRU recurrence. 128 CTAs x 256 threads, 1 wave.
// CTA owns SLICE=8 h-columns; w_hh rows (r,z,n slices) resident in SMEM.
// h kept transposed [k][b] so batch is contiguous (f32x2 along batch).
// Thread layout: tid = kq*64 + og*16 + bg  (split-K x4, 6 outputs, 4 batches)
// ===========================================================================
#define SM2_W   (24 * 1024 * 4)                     // 98304 B
#define SM2_RED (4 * 24 * 16 * 16)                  // 24576 B  (ulonglong2)
#define SM2_GH  (24 * 64 * 4)                       // 6144 B
#define SM2_TOT (SM2_W + SM2_RED + SM2_GH + 128)

__global__ __launch_bounds__(256, 1) void gru_rec(const float *__restrict__ w_hh,
                                                  const float *__restrict__ b_hh) {
    extern __shared__ __align__(16) char smem[];
    float      *sW   = (float *)smem;                          // [24][1024]
    ulonglong2 *sRed = (ulonglong2 *)(smem + SM2_W);           // [4][24][16]
    float      *sGh  = (float *)(smem + SM2_W + SM2_RED);      // [24][64]
    float      *sBhh = (float *)(smem + SM2_W + SM2_RED + SM2_GH); // [24]

    const int tid = threadIdx.x;
    const int c0  = blockIdx.x * SLICE;

    // --- load this CTA's w_hh rows into SMEM (persistent across all 512 steps)
    for (int i = tid; i < 24 * 256; i += 256) {          // float4 granularity
        int o = i >> 8, kk = (i & 255) << 2;
        int g = o >> 3, j = o & 7;
        float4 v = *(const float4 *)(w_hh + (long long)(g * H_ + c0 + j) * H_ + kk);
        *(float4 *)(sW + o * 1024 + kk) = v;
    }
    if (tid < 24) sBhh[tid] = b_hh[(tid >> 3) * H_ + c0 + (tid & 7)];

    // --- zero h buffer 0 (must happen every launch / replay)
    for (int i = tid; i < SLICE * B_; i += 256) {
        int c = i >> 6, b = i & 63;
        g_hT[0][(c0 + c) * B_ + b] = 0.f;
    }
    grid_sync();

    const int kq = tid >> 6;          // 0..3  split-K quarter
    const int og = (tid >> 4) & 3;    // 0..3  output group (6 rows each)
    const int bg = tid & 15;          // 0..15 batch group (4 batches)
    const float *wb = sW + og * 6 * 1024;
    const int k0 = kq << 8;

    for (int t = 0; t < T_; ++t) {
        const float *hbuf = g_hT[t & 1];
        float       *hout = g_hT[(t & 1) ^ 1];

        // prefetch gi for the pointwise phase (hides DRAM latency behind dots)
        float gia[3], gib[3];
        {
            int c = tid >> 6, b = tid & 63;
            const float *p = g_gi + (long long)(t * B_ + b) * G3 + c0 + c;
            gia[0] = __ldg(p); gia[1] = __ldg(p + H_); gia[2] = __ldg(p + 2 * H_);
            int idx = tid + 256; c = idx >> 6; b = idx & 63;
            p = g_gi + (long long)(t * B_ + b) * G3 + c0 + c;
            gib[0] = __ldg(p); gib[1] = __ldg(p + H_); gib[2] = __ldg(p + 2 * H_);
        }

        // --- gh partial dots: 6 outputs x 4 batches over 256 k
        u64 acc[6][2];
#pragma unroll
        for (int o = 0; o < 6; ++o) { acc[o][0] = 0ull; acc[o][1] = 0ull; }

#pragma unroll 4
        for (int k = k0; k < k0 + 256; ++k) {
            u64 hx, hy;
            const float *hp = hbuf + k * B_ + bg * 4;
            // .cg: bypass non-coherent L1 (buffer rewritten every other step)
            asm volatile("ld.global.cg.v2.u64 {%0,%1}, [%2];"
                         : "=l"(hx), "=l"(hy) : "l"(hp));
#pragma unroll
            for (int o = 0; o < 6; ++o) {
                float w = wb[o * 1024 + k];
                u64 w2 = pack2(w, w);
                fma2(acc[o][0], w2, hx);
                fma2(acc[o][1], w2, hy);
            }
        }

        // --- split-K reduction into sGh[24][64]
#pragma unroll
        for (int o = 0; o < 6; ++o)
            sRed[(kq * 24 + og * 6 + o) * 16 + bg] =
                make_ulonglong2(acc[o][0], acc[o][1]);
        __syncthreads();
        if (tid < 64) {
            int bg2 = tid & 15, og2 = tid >> 4;
#pragma unroll
            for (int o = 0; o < 6; ++o) {
                int row = og2 * 6 + o;
                ulonglong2 r0 = sRed[(0 * 24 + row) * 16 + bg2];
                ulonglong2 r1 = sRed[(1 * 24 + row) * 16 + bg2];
                ulonglong2 r2 = sRed[(2 * 24 + row) * 16 + bg2];
                ulonglong2 r3 = sRed[(3 * 24 + row) * 16 + bg2];
                u64 sx = add2(add2(r0.x, r1.x), add2(r2.x, r3.x));
                u64 sy = add2(add2(r0.y, r1.y), add2(r2.y, r3.y));
                float2 a = unpack2(sx), b2 = unpack2(sy);
                float4 v; v.x = a.x; v.y = a.y; v.z = b2.x; v.w = b2.y;
                *(float4 *)(sGh + row * 64 + bg2 * 4) = v;
            }
        }
        __syncthreads();

        // --- pointwise GRU gate math: 512 (c,b) cells, 2 per thread
#pragma unroll
        for (int half = 0; half < 2; ++half) {
            int idx = tid + half * 256;
            int c = idx >> 6, b = idx & 63;
            const float *gi = half ? gib : gia;
            float ghr = sGh[(c)       * 64 + b] + sBhh[c];
            float ghz = sGh[(8 + c)   * 64 + b] + sBhh[8 + c];
            float ghn = sGh[(16 + c)  * 64 + b] + sBhh[16 + c];
            float r = 1.f / (1.f + __expf(-(gi[0] + ghr)));
            float z = 1.f / (1.f + __expf(-(gi[1] + ghz)));
            float n = tanhf(gi[2] + r * ghn);
            float hp;
            asm volatile("ld.global.cg.f32 %0, [%1];"
                         : "=f"(hp) : "l"(hbuf + (c0 + c) * B_ + b));
            float hn = (1.f - z) * n + z * hp;
            hout[(c0 + c) * B_ + b] = hn;
            g_hs[(long long)(t * B_ + b) * H_ + c0 + c] = hn;
        }

        grid_sync();
    }
}

// ===========================================================================
// Kernel 3: pred[b][t][c] = g_hs[token] . cls_w[c] + cls_b[c]
// 512 blocks x 256 thr; thread = (token_local, kq); cls_w transposed in SMEM.
// ===========================================================================
#define SM3_TOT (1024 * 20 * 4 + 128)

__global__ __launch_bounds__(256) void cls_gemm(const float *__restrict__ cls_w,
                                                const float *__restrict__ cls_b,
                                                float *__restrict__ out) {
    extern __shared__ __align__(16) char sm3[];
    float *sWc   = (float *)sm3;            // [1024][20] (k-major, cls pairs)
    float *sBias = sWc + 1024 * 20;

    const int tid = threadIdx.x;
    for (int i = tid; i < 1024 * 20; i += 256) {
        int c = i / 1024, k = i - c * 1024;
        sWc[k * 20 + c] = cls_w[i];
    }
    if (tid < 20) sBias[tid] = cls_b[tid];
    __syncthreads();

    const int tokl = tid >> 2, kq = tid & 3;
    const int token = blockIdx.x * 64 + tokl;
    const float *hrow = g_hs + (long long)token * H_ + kq * 256;

    u64 acc[10];
#pragma unroll
    for (int c = 0; c < 10; ++c) acc[c] = 0ull;

    for (int k = 0; k < 256; k += 4) {
        float4 hv = *(const float4 *)(hrow + k);
        float hs4[4] = {hv.x, hv.y, hv.z, hv.w};
#pragma unroll
        for (int i = 0; i < 4; ++i) {
            u64 h2 = pack2(hs4[i], hs4[i]);
            const u64 *wr = (const u64 *)(sWc + (kq * 256 + k + i) * 20);
#pragma unroll
            for (int c = 0; c < 10; ++c) fma2(acc[c], h2, wr[c]);
        }
    }
    // reduce the 4 split-K lanes (adjacent lanes in warp)
#pragma unroll
    for (int c = 0; c < 10; ++c) {
        acc[c] = add2(acc[c], __shfl_xor_sync(0xffffffffu, acc[c], 1));
        acc[c] = add2(acc[c], __shfl_xor_sync(0xffffffffu, acc[c], 2));
    }
    if (kq == 0) {
        int t = token >> 6, b = token & 63;
        float *op = out + (long long)(b * T_ + t) * NC;
#pragma unroll
        for (int c = 0; c < 10; ++c) {
            float2 p = unpack2(acc[c]);
            op[2 * c]     = p.x + sBias[2 * c];
            op[2 * c + 1] = p.y + sBias[2 * c + 1];
        }
    }
}

// ===========================================================================
extern "C" void kernel_launch(void *const *d_in, const int *in_sizes, int n_in,
                              void *d_out, int out_size) {
    const int   *x     = (const int *)d_in[0];
    const float *emb   = (const float *)d_in[1];
    const float *w_ih  = (const float *)d_in[2];
    const float *w_hh  = (const float *)d_in[3];
    const float *b_ih  = (const float *)d_in[4];
    const float *b_hh  = (const float *)d_in[5];
    const float *cls_w = (const float *)d_in[6];
    const float *cls_b = (const float *)d_in[7];
    float *out = (float *)d_out;

    cudaFuncSetAttribute(gru_rec, cudaFuncAttributeMaxDynamicSharedMemorySize, SM2_TOT);
    cudaFuncSetAttribute(cls_gemm, cudaFuncAttributeMaxDynamicSharedMemorySize, SM3_TOT);

    dim3 g1(G3 / 64, (T_ * B_) / 128);          // (48, 256)
    gi_gemm<<<g1, 256>>>(x, emb, w_ih, b_ih);
    gru_rec<<<NCTA2, 256, SM2_TOT>>>(w_hh, b_hh);
    cls_gemm<<<(T_ * B_) / 64, 256, SM3_TOT>>>(cls_w, cls_b, out);
}